// round 1
// baseline (speedup 1.0000x reference)
#include <cuda_runtime.h>
#include <math.h>

// Problem constants
#define BB   2
#define NN   4096
#define BNP  (BB*NN)        // 8192 rows
#define DIMV 256
#define KNNV 16
#define M2   (BNP*KNNV)     // 131072 rows for per-neighbor tensors

// -------------------- scratch (no allocations allowed) --------------------
__device__ float g_q  [BNP*DIMV];
__device__ float g_k  [BNP*DIMV];
__device__ float g_v  [BNP*DIMV];
__device__ float g_agg[BNP*DIMV];
__device__ int   g_idx[M2];
__device__ float g_buf1[(size_t)M2*DIMV];  // h, then a_in, then a2
__device__ float g_buf2[(size_t)M2*DIMV];  // h2
__device__ float g_pe  [(size_t)M2*DIMV];  // pos_enc

// -------------------- generic fp32 GEMM: C = act(A@W + bias) (+resid) -----
// A: M x 256 row-major, W: 256 x 256 row-major, C: M x 256. M % 128 == 0.
// Block tile 128x128, BK=16, 256 threads, 8x8 per thread.
__global__ __launch_bounds__(256, 2)
void gemm256_kernel(const float* __restrict__ A, const float* __restrict__ W,
                    const float* __restrict__ bias, const float* __restrict__ resid,
                    float* __restrict__ C, int M, int doRelu)
{
    __shared__ float As[16][128];   // transposed: As[k][m]
    __shared__ float Bs[16][128];   // Bs[k][n]

    const int tid = threadIdx.x;
    const int bm  = blockIdx.y * 128;
    const int bn  = blockIdx.x * 128;
    const int tm  = (tid >> 4) * 8;   // 0..120
    const int tn  = (tid & 15) * 8;   // 0..120

    float acc[8][8];
#pragma unroll
    for (int i = 0; i < 8; ++i)
#pragma unroll
        for (int j = 0; j < 8; ++j) acc[i][j] = 0.f;

    for (int k0 = 0; k0 < 256; k0 += 16) {
        __syncthreads();
        // load A tile (128 rows x 16 cols) -> transposed into As
#pragma unroll
        for (int u = 0; u < 2; ++u) {
            int f  = tid * 2 + u;          // 0..511 float4 slots
            int ar = f >> 2;               // row 0..127
            int ac = (f & 3) * 4;          // col 0,4,8,12
            float4 vv = *(const float4*)(A + (size_t)(bm + ar) * 256 + k0 + ac);
            As[ac + 0][ar] = vv.x;
            As[ac + 1][ar] = vv.y;
            As[ac + 2][ar] = vv.z;
            As[ac + 3][ar] = vv.w;
        }
        // load B tile (16 rows x 128 cols) straight copy
#pragma unroll
        for (int u = 0; u < 2; ++u) {
            int f  = tid * 2 + u;
            int br = f >> 5;               // 0..15
            int bc = (f & 31) * 4;         // 0..124
            *(float4*)(&Bs[br][bc]) =
                *(const float4*)(W + (size_t)(k0 + br) * 256 + bn + bc);
        }
        __syncthreads();
#pragma unroll
        for (int k = 0; k < 16; ++k) {
            float af[8], bf[8];
            *(float4*)(af)     = *(const float4*)(&As[k][tm]);
            *(float4*)(af + 4) = *(const float4*)(&As[k][tm + 4]);
            *(float4*)(bf)     = *(const float4*)(&Bs[k][tn]);
            *(float4*)(bf + 4) = *(const float4*)(&Bs[k][tn + 4]);
#pragma unroll
            for (int i = 0; i < 8; ++i)
#pragma unroll
                for (int j = 0; j < 8; ++j)
                    acc[i][j] = fmaf(af[i], bf[j], acc[i][j]);
        }
    }

    // epilogue
#pragma unroll
    for (int i = 0; i < 8; ++i) {
        size_t row = (size_t)(bm + tm + i);
#pragma unroll
        for (int j4 = 0; j4 < 8; j4 += 4) {
            float4 o;
            float* op = &o.x;
#pragma unroll
            for (int j = 0; j < 4; ++j) {
                float c = acc[i][j4 + j];
                if (bias)  c += bias[bn + tn + j4 + j];
                if (doRelu) c = fmaxf(c, 0.f);
                if (resid) c += resid[row * 256 + bn + tn + j4 + j];
                op[j] = c;
            }
            *(float4*)(C + row * 256 + bn + tn + j4) = o;
        }
    }
}

// -------------------- KNN: one warp per query --------------------
__device__ __forceinline__ bool dless(float d1, int i1, float d2, int i2) {
    return (d1 < d2) || (d1 == d2 && i1 < i2);
}

__global__ __launch_bounds__(256)
void knn_kernel(const float* __restrict__ pos)
{
    __shared__ float px[NN], py[NN], pz[NN];   // 48KB
    const int b = blockIdx.x >> 9;             // 512 blocks per batch
    const float* pb = pos + (size_t)b * NN * 3;
    for (int j = threadIdx.x; j < NN; j += 256) {
        px[j] = pb[3 * j];
        py[j] = pb[3 * j + 1];
        pz[j] = pb[3 * j + 2];
    }
    __syncthreads();

    const int warp = threadIdx.x >> 5, lane = threadIdx.x & 31;
    const int q  = blockIdx.x * 8 + warp;       // global query
    const int ql = q & (NN - 1);
    const float qx = px[ql], qy = py[ql], qz = pz[ql];
    const float qsq = qx * qx + qy * qy + qz * qz;

    float bd[KNNV];
    int   bi[KNNV];
#pragma unroll
    for (int t = 0; t < KNNV; ++t) { bd[t] = 3.4e38f; bi[t] = 0x7fffffff; }

    for (int j = lane; j < NN; j += 32) {
        float x = px[j], y = py[j], z = pz[j];
        float sj  = x * x + y * y + z * z;
        float dot = qx * x + qy * y + qz * z;
        float d = qsq + sj - 2.f * dot;          // same expansion as reference
        if (dless(d, j, bd[KNNV - 1], bi[KNNV - 1])) {
#pragma unroll
            for (int t = KNNV - 1; t >= 1; --t) {
                bool cT   = dless(d, j, bd[t],     bi[t]);
                bool cTm1 = dless(d, j, bd[t - 1], bi[t - 1]);
                if (cT) {
                    bd[t] = cTm1 ? bd[t - 1] : d;
                    bi[t] = cTm1 ? bi[t - 1] : j;
                }
            }
            if (dless(d, j, bd[0], bi[0])) { bd[0] = d; bi[0] = j; }
        }
    }

    // merge 32 sorted lists -> global top-16
    const unsigned full = 0xffffffffu;
#pragma unroll 1
    for (int r = 0; r < KNNV; ++r) {
        float d = bd[0]; int id = bi[0];
#pragma unroll
        for (int off = 16; off; off >>= 1) {
            float od = __shfl_down_sync(full, d, off);
            int   oi = __shfl_down_sync(full, id, off);
            if (dless(od, oi, d, id)) { d = od; id = oi; }
        }
        float wd = __shfl_sync(full, d, 0);
        int   wi = __shfl_sync(full, id, 0);
        if (bd[0] == wd && bi[0] == wi) {   // unique: lane owns j%32
#pragma unroll
            for (int t = 0; t < KNNV - 1; ++t) { bd[t] = bd[t + 1]; bi[t] = bi[t + 1]; }
            bd[KNNV - 1] = 3.4e38f; bi[KNNV - 1] = 0x7fffffff;
        }
        if (lane == 0) g_idx[q * KNNV + r] = b * NN + wi;  // store GLOBAL row
    }
}

// ---------- h = relu(rel @ pw1 + pb1), rel = pos[n] - pos[neigh] ----------
__global__ __launch_bounds__(256)
void build_h_kernel(const float* __restrict__ pos, const float* __restrict__ pw1,
                    const float* __restrict__ pb1)
{
    const int m = blockIdx.x;          // 0..M2-1
    const int d = threadIdx.x;
    const int n = m >> 4;              // global query row
    const int r = g_idx[m];            // global neighbor row
    const float rx = pos[3 * n]     - pos[3 * r];
    const float ry = pos[3 * n + 1] - pos[3 * r + 1];
    const float rz = pos[3 * n + 2] - pos[3 * r + 2];
    float v = pb1[d] + rx * pw1[d] + ry * pw1[DIMV + d] + rz * pw1[2 * DIMV + d];
    g_buf1[(size_t)m * DIMV + d] = fmaxf(v, 0.f);
}

// ---------- a_in = q[n] - kfeat[neigh] + pos_enc  (into g_buf1) ----------
__global__ __launch_bounds__(256)
void a_in_kernel()
{
    const int m = blockIdx.x;
    const int d = threadIdx.x;
    const int n = m >> 4;
    const int r = g_idx[m];
    g_buf1[(size_t)m * DIMV + d] =
        g_q[(size_t)n * DIMV + d] - g_k[(size_t)r * DIMV + d] + g_pe[(size_t)m * DIMV + d];
}

// ---------- softmax over K (per channel) + weighted aggregate ----------
__global__ __launch_bounds__(256)
void softmax_agg_kernel()
{
    const int n = blockIdx.x;          // 0..8191
    const int d = threadIdx.x;
    const float inv_scale = 1.0f / 16.0f;   // 1/sqrt(256)

    float a[KNNV];
    float mx = -3.4e38f;
#pragma unroll
    for (int kk = 0; kk < KNNV; ++kk) {
        a[kk] = g_buf1[((size_t)(n * KNNV + kk)) * DIMV + d] * inv_scale;
        mx = fmaxf(mx, a[kk]);
    }
    float s = 0.f;
#pragma unroll
    for (int kk = 0; kk < KNNV; ++kk) {
        float e = expf(a[kk] - mx);
        a[kk] = e;
        s += e;
    }
    const float invs = 1.f / s;
    float acc = 0.f;
#pragma unroll
    for (int kk = 0; kk < KNNV; ++kk) {
        int r = g_idx[n * KNNV + kk];
        acc += a[kk] * (g_v[(size_t)r * DIMV + d] +
                        g_pe[((size_t)(n * KNNV + kk)) * DIMV + d]);
    }
    g_agg[(size_t)n * DIMV + d] = acc * invs;
}

// -------------------- launch --------------------
extern "C" void kernel_launch(void* const* d_in, const int* in_sizes, int n_in,
                              void* d_out, int out_size)
{
    const float* x   = (const float*)d_in[0];
    const float* pos = (const float*)d_in[1];
    const float* wq  = (const float*)d_in[2];
    const float* wk  = (const float*)d_in[3];
    const float* wv  = (const float*)d_in[4];
    const float* pw1 = (const float*)d_in[5];
    const float* pb1 = (const float*)d_in[6];
    const float* pw2 = (const float*)d_in[7];
    const float* pb2 = (const float*)d_in[8];
    const float* aw1 = (const float*)d_in[9];
    const float* ab1 = (const float*)d_in[10];
    const float* aw2 = (const float*)d_in[11];
    const float* ab2 = (const float*)d_in[12];
    const float* fw  = (const float*)d_in[13];
    const float* fb  = (const float*)d_in[14];
    (void)in_sizes; (void)n_in; (void)out_size;

    float *q, *k, *v, *agg, *buf1, *buf2, *pe;
    cudaGetSymbolAddress((void**)&q,    g_q);
    cudaGetSymbolAddress((void**)&k,    g_k);
    cudaGetSymbolAddress((void**)&v,    g_v);
    cudaGetSymbolAddress((void**)&agg,  g_agg);
    cudaGetSymbolAddress((void**)&buf1, g_buf1);
    cudaGetSymbolAddress((void**)&buf2, g_buf2);
    cudaGetSymbolAddress((void**)&pe,   g_pe);

    dim3 blk(256);
    dim3 gSmall(2, BNP / 128);     // (2, 64)
    dim3 gBig(2, M2 / 128);        // (2, 1024)

    // q, k, v projections
    gemm256_kernel<<<gSmall, blk>>>(x, wq, nullptr, nullptr, q, BNP, 0);
    gemm256_kernel<<<gSmall, blk>>>(x, wk, nullptr, nullptr, k, BNP, 0);
    gemm256_kernel<<<gSmall, blk>>>(x, wv, nullptr, nullptr, v, BNP, 0);

    // knn
    knn_kernel<<<BNP / 8, blk>>>(pos);

    // pos_enc path: h = relu(rel@pw1+pb1) ; pe = h@pw2+pb2
    build_h_kernel<<<M2, blk>>>(pos, pw1, pb1);
    gemm256_kernel<<<gBig, blk>>>(buf1, pw2, pb2, nullptr, pe, M2, 0);

    // attention MLP: a_in = q - k[idx] + pe ; h2 = relu(a_in@aw1+ab1) ; a2 = h2@aw2+ab2
    a_in_kernel<<<M2, blk>>>();
    gemm256_kernel<<<gBig, blk>>>(buf1, aw1, ab1, nullptr, buf2, M2, 1);
    gemm256_kernel<<<gBig, blk>>>(buf2, aw2, ab2, nullptr, buf1, M2, 0);

    // softmax over K + aggregate
    softmax_agg_kernel<<<BNP, blk>>>();

    // out = agg@fw + fb + x
    gemm256_kernel<<<gSmall, blk>>>(agg, fw, fb, x, (float*)d_out, BNP, 0);
}

// round 2
// speedup vs baseline: 1.7949x; 1.7949x over previous
#include <cuda_runtime.h>
#include <math.h>
#include <stdint.h>

// Problem constants
#define BB   2
#define NN   4096
#define BNP  (BB*NN)        // 8192 rows
#define DIMV 256
#define KNNV 16
#define M2   (BNP*KNNV)     // 131072 rows for per-neighbor tensors

// -------------------- scratch (no allocations allowed) --------------------
__device__ float g_q  [BNP*DIMV];
__device__ float g_k  [BNP*DIMV];
__device__ float g_v  [BNP*DIMV];
__device__ float g_agg[BNP*DIMV];
__device__ int   g_idx[M2];
__device__ float g_buf1[(size_t)M2*DIMV];  // h, then a_in, then a2
__device__ float g_buf2[(size_t)M2*DIMV];  // h2
__device__ float g_pe  [(size_t)M2*DIMV];  // pos_enc

// ==================== tf32 tensor-core GEMM ====================
// C = act(A@W + bias) (+resid).  A: M x 256, W: 256 x 256 row-major.
// CTA tile 128x128, BK=32. 8 warps (2 x 4). mma.sync.m16n8k8 tf32.
// Dynamic smem: As[2][128][36] + Bs[2][32][132] floats = 70656 B.

#define AS_STRIDE 36
#define BS_STRIDE 132
#define AS_BUF (128*AS_STRIDE)   // 4608 floats
#define BS_BUF (32*BS_STRIDE)    // 4224 floats
#define GEMM_SMEM_BYTES ((2*AS_BUF + 2*BS_BUF) * 4)

__device__ __forceinline__ void cp16(float* s, const float* g) {
    uint32_t sa = (uint32_t)__cvta_generic_to_shared(s);
    asm volatile("cp.async.cg.shared.global [%0], [%1], 16;\n" :: "r"(sa), "l"(g));
}
__device__ __forceinline__ void cp_commit() {
    asm volatile("cp.async.commit_group;\n");
}
__device__ __forceinline__ uint32_t f2tf32(float f) {
    uint32_t u;
    asm("cvt.rna.tf32.f32 %0, %1;\n" : "=r"(u) : "f"(f));
    return u;
}

__global__ __launch_bounds__(256)
void gemm_tf32_kernel(const float* __restrict__ A, const float* __restrict__ W,
                      const float* __restrict__ bias, const float* __restrict__ resid,
                      float* __restrict__ C, int M, int doRelu)
{
    extern __shared__ float smem[];
    float* As = smem;                 // [2][128][36]
    float* Bs = smem + 2 * AS_BUF;    // [2][32][132]

    const int tid  = threadIdx.x;
    const int lane = tid & 31;
    const int warp = tid >> 5;
    const int wm   = warp >> 2;       // 0..1  -> 64 rows
    const int wn   = warp & 3;        // 0..3  -> 32 cols
    const int bm   = blockIdx.y * 128;
    const int bn   = blockIdx.x * 128;

    const int g  = lane >> 2;         // groupID 0..7
    const int tg = lane & 3;          // thread-in-group 0..3

    float acc[4][4][4];
#pragma unroll
    for (int i = 0; i < 4; ++i)
#pragma unroll
        for (int j = 0; j < 4; ++j)
#pragma unroll
            for (int c = 0; c < 4; ++c) acc[i][j][c] = 0.f;

    // tile loader: tile index t covers K cols [t*32, t*32+32)
    auto load_tile = [&](int buf, int k0) {
#pragma unroll
        for (int u = 0; u < 4; ++u) {
            int idx = tid + u * 256;          // 0..1023
            int row = idx >> 3;               // 0..127
            int c4  = (idx & 7) * 4;          // 0..28
            cp16(&As[buf * AS_BUF + row * AS_STRIDE + c4],
                 A + (size_t)(bm + row) * 256 + k0 + c4);
        }
#pragma unroll
        for (int u = 0; u < 4; ++u) {
            int idx = tid + u * 256;
            int kr  = idx >> 5;               // 0..31
            int c4  = (idx & 31) * 4;         // 0..124
            cp16(&Bs[buf * BS_BUF + kr * BS_STRIDE + c4],
                 W + (size_t)(k0 + kr) * 256 + bn + c4);
        }
        cp_commit();
    };

    load_tile(0, 0);

    for (int t = 0; t < 8; ++t) {
        const int buf = t & 1;
        if (t < 7) {
            load_tile(buf ^ 1, (t + 1) * 32);
            asm volatile("cp.async.wait_group 1;\n");
        } else {
            asm volatile("cp.async.wait_group 0;\n");
        }
        __syncthreads();

        const float* Ab = As + buf * AS_BUF;
        const float* Bb = Bs + buf * BS_BUF;

#pragma unroll
        for (int ks = 0; ks < 4; ++ks) {
            const int k0 = ks * 8;
            uint32_t af[4][4], bf[4][2];
#pragma unroll
            for (int mt = 0; mt < 4; ++mt) {
                int row = wm * 64 + mt * 16 + g;
                const float* ap = Ab + row * AS_STRIDE + k0 + tg;
                af[mt][0] = f2tf32(ap[0]);
                af[mt][1] = f2tf32(ap[8 * AS_STRIDE]);
                af[mt][2] = f2tf32(ap[4]);
                af[mt][3] = f2tf32(ap[8 * AS_STRIDE + 4]);
            }
#pragma unroll
            for (int nt = 0; nt < 4; ++nt) {
                int col = wn * 32 + nt * 8 + g;
                const float* bp = Bb + (k0 + tg) * BS_STRIDE + col;
                bf[nt][0] = f2tf32(bp[0]);
                bf[nt][1] = f2tf32(bp[4 * BS_STRIDE]);
            }
#pragma unroll
            for (int mt = 0; mt < 4; ++mt)
#pragma unroll
                for (int nt = 0; nt < 4; ++nt) {
                    asm volatile(
                        "mma.sync.aligned.m16n8k8.row.col.f32.tf32.tf32.f32 "
                        "{%0,%1,%2,%3}, {%4,%5,%6,%7}, {%8,%9}, {%0,%1,%2,%3};\n"
                        : "+f"(acc[mt][nt][0]), "+f"(acc[mt][nt][1]),
                          "+f"(acc[mt][nt][2]), "+f"(acc[mt][nt][3])
                        : "r"(af[mt][0]), "r"(af[mt][1]), "r"(af[mt][2]), "r"(af[mt][3]),
                          "r"(bf[nt][0]), "r"(bf[nt][1]));
                }
        }
        __syncthreads();
    }

    // epilogue
#pragma unroll
    for (int mt = 0; mt < 4; ++mt) {
#pragma unroll
        for (int nt = 0; nt < 4; ++nt) {
            int row0 = bm + wm * 64 + mt * 16 + g;
            int col0 = bn + wn * 32 + nt * 8 + 2 * tg;
#pragma unroll
            for (int h = 0; h < 2; ++h) {
                int row = row0 + h * 8;
                float c0 = acc[mt][nt][2 * h];
                float c1 = acc[mt][nt][2 * h + 1];
                if (bias) { c0 += bias[col0]; c1 += bias[col0 + 1]; }
                if (doRelu) { c0 = fmaxf(c0, 0.f); c1 = fmaxf(c1, 0.f); }
                if (resid) {
                    c0 += resid[(size_t)row * 256 + col0];
                    c1 += resid[(size_t)row * 256 + col0 + 1];
                }
                *(float2*)(C + (size_t)row * 256 + col0) = make_float2(c0, c1);
            }
        }
    }
}

// -------------------- KNN: one warp per query --------------------
__device__ __forceinline__ bool dless(float d1, int i1, float d2, int i2) {
    return (d1 < d2) || (d1 == d2 && i1 < i2);
}

#define KNN_SMEM_BYTES (4 * NN * 4)

__global__ __launch_bounds__(256)
void knn_kernel(const float* __restrict__ pos)
{
    extern __shared__ float sm[];
    float* px = sm;
    float* py = sm + NN;
    float* pz = sm + 2 * NN;
    float* sj = sm + 3 * NN;

    const int b = blockIdx.x >> 9;             // 512 blocks per batch
    const float* pb = pos + (size_t)b * NN * 3;
    for (int j = threadIdx.x; j < NN; j += 256) {
        float x = pb[3 * j], y = pb[3 * j + 1], z = pb[3 * j + 2];
        px[j] = x; py[j] = y; pz[j] = z;
        sj[j] = x * x + y * y + z * z;
    }
    __syncthreads();

    const int warp = threadIdx.x >> 5, lane = threadIdx.x & 31;
    const int q  = blockIdx.x * 8 + warp;       // global query
    const int ql = q & (NN - 1);
    const float qx = px[ql], qy = py[ql], qz = pz[ql];
    const float qsq = sj[ql];

    float bd[KNNV];
    int   bi[KNNV];
#pragma unroll
    for (int t = 0; t < KNNV; ++t) { bd[t] = 3.4e38f; bi[t] = 0x7fffffff; }

    for (int j = lane; j < NN; j += 32) {
        float dot = qx * px[j] + qy * py[j] + qz * pz[j];
        float d = qsq + sj[j] - 2.f * dot;       // same expansion as reference
        if (dless(d, j, bd[KNNV - 1], bi[KNNV - 1])) {
#pragma unroll
            for (int t = KNNV - 1; t >= 1; --t) {
                bool cT   = dless(d, j, bd[t],     bi[t]);
                bool cTm1 = dless(d, j, bd[t - 1], bi[t - 1]);
                if (cT) {
                    bd[t] = cTm1 ? bd[t - 1] : d;
                    bi[t] = cTm1 ? bi[t - 1] : j;
                }
            }
            if (dless(d, j, bd[0], bi[0])) { bd[0] = d; bi[0] = j; }
        }
    }

    // merge 32 sorted lists -> global top-16
    const unsigned full = 0xffffffffu;
#pragma unroll 1
    for (int r = 0; r < KNNV; ++r) {
        float d = bd[0]; int id = bi[0];
#pragma unroll
        for (int off = 16; off; off >>= 1) {
            float od = __shfl_down_sync(full, d, off);
            int   oi = __shfl_down_sync(full, id, off);
            if (dless(od, oi, d, id)) { d = od; id = oi; }
        }
        float wd = __shfl_sync(full, d, 0);
        int   wi = __shfl_sync(full, id, 0);
        if (bd[0] == wd && bi[0] == wi) {   // unique: lane owns j%32
#pragma unroll
            for (int t = 0; t < KNNV - 1; ++t) { bd[t] = bd[t + 1]; bi[t] = bi[t + 1]; }
            bd[KNNV - 1] = 3.4e38f; bi[KNNV - 1] = 0x7fffffff;
        }
        if (lane == 0) g_idx[q * KNNV + r] = b * NN + wi;  // store GLOBAL row
    }
}

// ---------- h = relu(rel @ pw1 + pb1), rel = pos[n] - pos[neigh] ----------
__global__ __launch_bounds__(256)
void build_h_kernel(const float* __restrict__ pos, const float* __restrict__ pw1,
                    const float* __restrict__ pb1)
{
    const int m = blockIdx.x;          // 0..M2-1
    const int d = threadIdx.x;
    const int n = m >> 4;              // global query row
    const int r = g_idx[m];            // global neighbor row
    const float rx = pos[3 * n]     - pos[3 * r];
    const float ry = pos[3 * n + 1] - pos[3 * r + 1];
    const float rz = pos[3 * n + 2] - pos[3 * r + 2];
    float v = pb1[d] + rx * pw1[d] + ry * pw1[DIMV + d] + rz * pw1[2 * DIMV + d];
    g_buf1[(size_t)m * DIMV + d] = fmaxf(v, 0.f);
}

// ---------- a_in = q[n] - kfeat[neigh] + pos_enc  (into g_buf1) ----------
__global__ __launch_bounds__(256)
void a_in_kernel()
{
    const int m = blockIdx.x;
    const int d = threadIdx.x;
    const int n = m >> 4;
    const int r = g_idx[m];
    g_buf1[(size_t)m * DIMV + d] =
        g_q[(size_t)n * DIMV + d] - g_k[(size_t)r * DIMV + d] + g_pe[(size_t)m * DIMV + d];
}

// ---------- softmax over K (per channel) + weighted aggregate ----------
__global__ __launch_bounds__(256)
void softmax_agg_kernel()
{
    const int n = blockIdx.x;          // 0..8191
    const int d = threadIdx.x;
    const float inv_scale = 1.0f / 16.0f;   // 1/sqrt(256)

    float a[KNNV];
    float mx = -3.4e38f;
#pragma unroll
    for (int kk = 0; kk < KNNV; ++kk) {
        a[kk] = g_buf1[((size_t)(n * KNNV + kk)) * DIMV + d] * inv_scale;
        mx = fmaxf(mx, a[kk]);
    }
    float s = 0.f;
#pragma unroll
    for (int kk = 0; kk < KNNV; ++kk) {
        float e = expf(a[kk] - mx);
        a[kk] = e;
        s += e;
    }
    const float invs = 1.f / s;
    float acc = 0.f;
#pragma unroll
    for (int kk = 0; kk < KNNV; ++kk) {
        int r = g_idx[n * KNNV + kk];
        acc += a[kk] * (g_v[(size_t)r * DIMV + d] +
                        g_pe[((size_t)(n * KNNV + kk)) * DIMV + d]);
    }
    g_agg[(size_t)n * DIMV + d] = acc * invs;
}

// -------------------- launch --------------------
extern "C" void kernel_launch(void* const* d_in, const int* in_sizes, int n_in,
                              void* d_out, int out_size)
{
    const float* x   = (const float*)d_in[0];
    const float* pos = (const float*)d_in[1];
    const float* wq  = (const float*)d_in[2];
    const float* wk  = (const float*)d_in[3];
    const float* wv  = (const float*)d_in[4];
    const float* pw1 = (const float*)d_in[5];
    const float* pb1 = (const float*)d_in[6];
    const float* pw2 = (const float*)d_in[7];
    const float* pb2 = (const float*)d_in[8];
    const float* aw1 = (const float*)d_in[9];
    const float* ab1 = (const float*)d_in[10];
    const float* aw2 = (const float*)d_in[11];
    const float* ab2 = (const float*)d_in[12];
    const float* fw  = (const float*)d_in[13];
    const float* fb  = (const float*)d_in[14];
    (void)in_sizes; (void)n_in; (void)out_size;

    float *q, *k, *v, *agg, *buf1, *buf2, *pe;
    cudaGetSymbolAddress((void**)&q,    g_q);
    cudaGetSymbolAddress((void**)&k,    g_k);
    cudaGetSymbolAddress((void**)&v,    g_v);
    cudaGetSymbolAddress((void**)&agg,  g_agg);
    cudaGetSymbolAddress((void**)&buf1, g_buf1);
    cudaGetSymbolAddress((void**)&buf2, g_buf2);
    cudaGetSymbolAddress((void**)&pe,   g_pe);

    cudaFuncSetAttribute(gemm_tf32_kernel,
                         cudaFuncAttributeMaxDynamicSharedMemorySize, GEMM_SMEM_BYTES);
    cudaFuncSetAttribute(knn_kernel,
                         cudaFuncAttributeMaxDynamicSharedMemorySize, KNN_SMEM_BYTES);

    dim3 blk(256);
    dim3 gSmall(2, BNP / 128);     // (2, 64)
    dim3 gBig(2, M2 / 128);        // (2, 1024)

    // q, k, v projections
    gemm_tf32_kernel<<<gSmall, blk, GEMM_SMEM_BYTES>>>(x, wq, nullptr, nullptr, q, BNP, 0);
    gemm_tf32_kernel<<<gSmall, blk, GEMM_SMEM_BYTES>>>(x, wk, nullptr, nullptr, k, BNP, 0);
    gemm_tf32_kernel<<<gSmall, blk, GEMM_SMEM_BYTES>>>(x, wv, nullptr, nullptr, v, BNP, 0);

    // knn
    knn_kernel<<<BNP / 8, blk, KNN_SMEM_BYTES>>>(pos);

    // pos_enc path: h = relu(rel@pw1+pb1) ; pe = h@pw2+pb2
    build_h_kernel<<<M2, blk>>>(pos, pw1, pb1);
    gemm_tf32_kernel<<<gBig, blk, GEMM_SMEM_BYTES>>>(buf1, pw2, pb2, nullptr, pe, M2, 0);

    // attention MLP: a_in = q - k[idx] + pe ; h2 = relu(a_in@aw1+ab1) ; a2 = h2@aw2+ab2
    a_in_kernel<<<M2, blk>>>();
    gemm_tf32_kernel<<<gBig, blk, GEMM_SMEM_BYTES>>>(buf1, aw1, ab1, nullptr, buf2, M2, 1);
    gemm_tf32_kernel<<<gBig, blk, GEMM_SMEM_BYTES>>>(buf2, aw2, ab2, nullptr, buf1, M2, 0);

    // softmax over K + aggregate
    softmax_agg_kernel<<<BNP, blk>>>();

    // out = agg@fw + fb + x
    gemm_tf32_kernel<<<gSmall, blk, GEMM_SMEM_BYTES>>>(agg, fw, fb, x, (float*)d_out, BNP, 0);
}

// round 3
// speedup vs baseline: 2.4215x; 1.3491x over previous
#include <cuda_runtime.h>
#include <math.h>
#include <stdint.h>

// Problem constants
#define BB   2
#define NN   4096
#define BNP  (BB*NN)        // 8192 rows
#define DIMV 256
#define KNNV 16
#define M2   (BNP*KNNV)     // 131072 rows for per-neighbor tensors

// -------------------- scratch (no allocations allowed) --------------------
__device__ float g_q  [BNP*DIMV];
__device__ float g_k  [BNP*DIMV];
__device__ float g_v  [BNP*DIMV];
__device__ float g_agg[BNP*DIMV];
__device__ int   g_idx[M2];
__device__ float g_buf1[(size_t)M2*DIMV];  // h, then a_in, then a2
__device__ float g_buf2[(size_t)M2*DIMV];  // h2
__device__ float g_pe  [(size_t)M2*DIMV];  // pos_enc
__device__ float g_wr [7*DIMV*DIMV];       // tf32-rounded weights
__device__ float g_xr [BNP*DIMV];          // tf32-rounded x

__device__ __forceinline__ uint32_t f2tf32(float f) {
    uint32_t u;
    asm("cvt.rna.tf32.f32 %0, %1;\n" : "=r"(u) : "f"(f));
    return u;
}
__device__ __forceinline__ float roundtf(float f) {
    return __uint_as_float(f2tf32(f));
}

// ==================== tf32 tensor-core GEMM ====================
// C = act(A@W + bias) (+resid).  A: M x 256 (PRE-ROUNDED to tf32),
// W: 256 x 256 row-major (PRE-ROUNDED). CTA tile 128x128, BK=32.
// 8 warps (2 x 4). mma.sync.m16n8k8 tf32.

#define AS_STRIDE 36
#define BS_STRIDE 132
#define AS_BUF (128*AS_STRIDE)   // 4608 floats
#define BS_BUF (32*BS_STRIDE)    // 4224 floats
#define GEMM_SMEM_BYTES ((2*AS_BUF + 2*BS_BUF) * 4)

__device__ __forceinline__ void cp16(float* s, const float* g) {
    uint32_t sa = (uint32_t)__cvta_generic_to_shared(s);
    asm volatile("cp.async.cg.shared.global [%0], [%1], 16;\n" :: "r"(sa), "l"(g));
}
__device__ __forceinline__ void cp_commit() {
    asm volatile("cp.async.commit_group;\n");
}

__global__ __launch_bounds__(256)
void gemm_tf32_kernel(const float* __restrict__ A, const float* __restrict__ W,
                      const float* __restrict__ bias, const float* __restrict__ resid,
                      float* __restrict__ C, int M, int doRelu, int doRound)
{
    extern __shared__ float smem[];
    float* As = smem;                 // [2][128][36]
    float* Bs = smem + 2 * AS_BUF;    // [2][32][132]

    const int tid  = threadIdx.x;
    const int lane = tid & 31;
    const int warp = tid >> 5;
    const int wm   = warp >> 2;       // 0..1  -> 64 rows
    const int wn   = warp & 3;        // 0..3  -> 32 cols
    const int bm   = blockIdx.y * 128;
    const int bn   = blockIdx.x * 128;

    const int g  = lane >> 2;         // groupID 0..7
    const int tg = lane & 3;          // thread-in-group 0..3

    float acc[4][4][4];
#pragma unroll
    for (int i = 0; i < 4; ++i)
#pragma unroll
        for (int j = 0; j < 4; ++j)
#pragma unroll
            for (int c = 0; c < 4; ++c) acc[i][j][c] = 0.f;

    auto load_tile = [&](int buf, int k0) {
#pragma unroll
        for (int u = 0; u < 4; ++u) {
            int idx = tid + u * 256;          // 0..1023
            int row = idx >> 3;               // 0..127
            int c4  = (idx & 7) * 4;          // 0..28
            cp16(&As[buf * AS_BUF + row * AS_STRIDE + c4],
                 A + (size_t)(bm + row) * 256 + k0 + c4);
        }
#pragma unroll
        for (int u = 0; u < 4; ++u) {
            int idx = tid + u * 256;
            int kr  = idx >> 5;               // 0..31
            int c4  = (idx & 31) * 4;         // 0..124
            cp16(&Bs[buf * BS_BUF + kr * BS_STRIDE + c4],
                 W + (size_t)(k0 + kr) * 256 + bn + c4);
        }
        cp_commit();
    };

    load_tile(0, 0);

    for (int t = 0; t < 8; ++t) {
        const int buf = t & 1;
        if (t < 7) {
            load_tile(buf ^ 1, (t + 1) * 32);
            asm volatile("cp.async.wait_group 1;\n");
        } else {
            asm volatile("cp.async.wait_group 0;\n");
        }
        __syncthreads();

        const float* Ab = As + buf * AS_BUF;
        const float* Bb = Bs + buf * BS_BUF;

#pragma unroll
        for (int ks = 0; ks < 4; ++ks) {
            const int k0 = ks * 8;
            uint32_t af[4][4], bf[4][2];
#pragma unroll
            for (int mt = 0; mt < 4; ++mt) {
                int row = wm * 64 + mt * 16 + g;
                const float* ap = Ab + row * AS_STRIDE + k0 + tg;
                af[mt][0] = __float_as_uint(ap[0]);
                af[mt][1] = __float_as_uint(ap[8 * AS_STRIDE]);
                af[mt][2] = __float_as_uint(ap[4]);
                af[mt][3] = __float_as_uint(ap[8 * AS_STRIDE + 4]);
            }
#pragma unroll
            for (int nt = 0; nt < 4; ++nt) {
                int col = wn * 32 + nt * 8 + g;
                const float* bp = Bb + (k0 + tg) * BS_STRIDE + col;
                bf[nt][0] = __float_as_uint(bp[0]);
                bf[nt][1] = __float_as_uint(bp[4 * BS_STRIDE]);
            }
#pragma unroll
            for (int mt = 0; mt < 4; ++mt)
#pragma unroll
                for (int nt = 0; nt < 4; ++nt) {
                    asm volatile(
                        "mma.sync.aligned.m16n8k8.row.col.f32.tf32.tf32.f32 "
                        "{%0,%1,%2,%3}, {%4,%5,%6,%7}, {%8,%9}, {%0,%1,%2,%3};\n"
                        : "+f"(acc[mt][nt][0]), "+f"(acc[mt][nt][1]),
                          "+f"(acc[mt][nt][2]), "+f"(acc[mt][nt][3])
                        : "r"(af[mt][0]), "r"(af[mt][1]), "r"(af[mt][2]), "r"(af[mt][3]),
                          "r"(bf[nt][0]), "r"(bf[nt][1]));
                }
        }
        __syncthreads();
    }

    // epilogue
#pragma unroll
    for (int mt = 0; mt < 4; ++mt) {
#pragma unroll
        for (int nt = 0; nt < 4; ++nt) {
            int row0 = bm + wm * 64 + mt * 16 + g;
            int col0 = bn + wn * 32 + nt * 8 + 2 * tg;
#pragma unroll
            for (int h = 0; h < 2; ++h) {
                int row = row0 + h * 8;
                float c0 = acc[mt][nt][2 * h];
                float c1 = acc[mt][nt][2 * h + 1];
                if (bias) { c0 += bias[col0]; c1 += bias[col0 + 1]; }
                if (doRelu) { c0 = fmaxf(c0, 0.f); c1 = fmaxf(c1, 0.f); }
                if (doRound) { c0 = roundtf(c0); c1 = roundtf(c1); }
                if (resid) {
                    c0 += resid[(size_t)row * 256 + col0];
                    c1 += resid[(size_t)row * 256 + col0 + 1];
                }
                *(float2*)(C + (size_t)row * 256 + col0) = make_float2(c0, c1);
            }
        }
    }
}

// -------------------- tf32 pre-rounding prep --------------------
struct RoundSrcs { const float* p[8]; };   // 7 weights (65536 each) + x

__global__ __launch_bounds__(256)
void round_prep_kernel(RoundSrcs srcs)
{
    const int idx4 = blockIdx.x * 256 + threadIdx.x;   // float4 index
    const int W4 = 7 * (DIMV * DIMV / 4);              // 114688
    const int X4 = BNP * DIMV / 4;                     // 524288
    if (idx4 < W4) {
        int seg = idx4 >> 14;            // 16384 float4 per weight
        int off = (idx4 & 16383) * 4;
        float4 v = *(const float4*)(srcs.p[seg] + off);
        v.x = roundtf(v.x); v.y = roundtf(v.y); v.z = roundtf(v.z); v.w = roundtf(v.w);
        *(float4*)(g_wr + seg * 65536 + off) = v;
    } else if (idx4 < W4 + X4) {
        int off = (idx4 - W4) * 4;
        float4 v = *(const float4*)(srcs.p[7] + off);
        v.x = roundtf(v.x); v.y = roundtf(v.y); v.z = roundtf(v.z); v.w = roundtf(v.w);
        *(float4*)(g_xr + off) = v;
    }
}

// -------------------- KNN: warp-collective threshold top-16 --------------------
__device__ __forceinline__ bool dless(float d1, int i1, float d2, int i2) {
    return (d1 < d2) || (d1 == d2 && i1 < i2);
}

#define KNN_SMEM_BYTES (4 * NN * 4)

__global__ __launch_bounds__(256)
void knn_kernel(const float* __restrict__ pos)
{
    extern __shared__ float sm[];
    float* px = sm;
    float* py = sm + NN;
    float* pz = sm + 2 * NN;
    float* sj = sm + 3 * NN;

    const int b = blockIdx.x >> 9;             // 512 blocks per batch
    const float* pb = pos + (size_t)b * NN * 3;
    for (int j = threadIdx.x; j < NN; j += 256) {
        float x = pb[3 * j], y = pb[3 * j + 1], z = pb[3 * j + 2];
        px[j] = x; py[j] = y; pz[j] = z;
        sj[j] = x * x + y * y + z * z;
    }
    __syncthreads();

    const int warp = threadIdx.x >> 5, lane = threadIdx.x & 31;
    const int q  = blockIdx.x * 8 + warp;       // global query
    const int ql = q & (NN - 1);
    const float qx = px[ql], qy = py[ql], qz = pz[ql];
    const float qsq = sj[ql];

    const unsigned FULL = 0xffffffffu;
    // warp-distributed sorted top-16: lane i (<16) holds i-th smallest
    float ld  = 3.4e38f; int li   = 0x7fffffff;
    float tau = 3.4e38f; int taui = 0x7fffffff;   // = list[15], warp-uniform

    // serial warp-wide insert of candidate (cd, cj); all lanes participate
#define KNN_INSERT(cd, cj)                                             \
    {                                                                  \
        bool keep = dless(ld, li, (cd), (cj));                         \
        unsigned bal = __ballot_sync(FULL, keep) & 0xffffu;            \
        int p = __popc(bal);                                           \
        float pd = __shfl_up_sync(FULL, ld, 1);                        \
        int   pi = __shfl_up_sync(FULL, li, 1);                        \
        if (lane == p) { ld = (cd); li = (cj); }                       \
        else if (lane > p && lane < 16) { ld = pd; li = pi; }          \
        tau  = __shfl_sync(FULL, ld, 15);                              \
        taui = __shfl_sync(FULL, li, 15);                              \
    }

#define KNN_HANDLE(dd, jj)                                             \
    {                                                                  \
        unsigned any = __ballot_sync(FULL, dless(dd, jj, tau, taui));  \
        while (any) {                                                  \
            int src = __ffs(any) - 1; any &= any - 1;                  \
            float cd = __shfl_sync(FULL, dd, src);                     \
            int   cj = __shfl_sync(FULL, jj, src);                     \
            if (dless(cd, cj, tau, taui)) KNN_INSERT(cd, cj);          \
        }                                                              \
    }

    for (int base = 0; base < NN; base += 128) {
        const int j0 = base + lane;
        const int j1 = j0 + 32;
        const int j2 = j0 + 64;
        const int j3 = j0 + 96;
        float d0 = qsq + sj[j0] - 2.f * (qx * px[j0] + qy * py[j0] + qz * pz[j0]);
        float d1 = qsq + sj[j1] - 2.f * (qx * px[j1] + qy * py[j1] + qz * pz[j1]);
        float d2 = qsq + sj[j2] - 2.f * (qx * px[j2] + qy * py[j2] + qz * pz[j2]);
        float d3 = qsq + sj[j3] - 2.f * (qx * px[j3] + qy * py[j3] + qz * pz[j3]);
        KNN_HANDLE(d0, j0)
        KNN_HANDLE(d1, j1)
        KNN_HANDLE(d2, j2)
        KNN_HANDLE(d3, j3)
    }

    if (lane < KNNV) g_idx[q * KNNV + lane] = b * NN + li;
#undef KNN_INSERT
#undef KNN_HANDLE
}

// ---------- h = relu(rel @ pw1 + pb1), rel = pos[n] - pos[neigh] ----------
__global__ __launch_bounds__(256)
void build_h_kernel(const float* __restrict__ pos, const float* __restrict__ pw1,
                    const float* __restrict__ pb1)
{
    const int m = blockIdx.x;          // 0..M2-1
    const int d = threadIdx.x;
    const int n = m >> 4;              // global query row
    const int r = g_idx[m];            // global neighbor row
    const float rx = pos[3 * n]     - pos[3 * r];
    const float ry = pos[3 * n + 1] - pos[3 * r + 1];
    const float rz = pos[3 * n + 2] - pos[3 * r + 2];
    float v = pb1[d] + rx * pw1[d] + ry * pw1[DIMV + d] + rz * pw1[2 * DIMV + d];
    g_buf1[(size_t)m * DIMV + d] = roundtf(fmaxf(v, 0.f));
}

// ---------- a_in = q[n] - kfeat[neigh] + pos_enc  (into g_buf1) ----------
__global__ __launch_bounds__(256)
void a_in_kernel()
{
    const int m = blockIdx.x;
    const int d = threadIdx.x;
    const int n = m >> 4;
    const int r = g_idx[m];
    g_buf1[(size_t)m * DIMV + d] = roundtf(
        g_q[(size_t)n * DIMV + d] - g_k[(size_t)r * DIMV + d] + g_pe[(size_t)m * DIMV + d]);
}

// ---------- softmax over K (per channel) + weighted aggregate ----------
__global__ __launch_bounds__(256)
void softmax_agg_kernel()
{
    const int n = blockIdx.x;          // 0..8191
    const int d = threadIdx.x;
    const float inv_scale = 1.0f / 16.0f;   // 1/sqrt(256)

    float a[KNNV];
    float mx = -3.4e38f;
#pragma unroll
    for (int kk = 0; kk < KNNV; ++kk) {
        a[kk] = g_buf1[((size_t)(n * KNNV + kk)) * DIMV + d] * inv_scale;
        mx = fmaxf(mx, a[kk]);
    }
    float s = 0.f;
#pragma unroll
    for (int kk = 0; kk < KNNV; ++kk) {
        float e = expf(a[kk] - mx);
        a[kk] = e;
        s += e;
    }
    const float invs = 1.f / s;
    float acc = 0.f;
#pragma unroll
    for (int kk = 0; kk < KNNV; ++kk) {
        int r = g_idx[n * KNNV + kk];
        acc += a[kk] * (g_v[(size_t)r * DIMV + d] +
                        g_pe[((size_t)(n * KNNV + kk)) * DIMV + d]);
    }
    g_agg[(size_t)n * DIMV + d] = roundtf(acc * invs);
}

// -------------------- launch --------------------
extern "C" void kernel_launch(void* const* d_in, const int* in_sizes, int n_in,
                              void* d_out, int out_size)
{
    const float* x   = (const float*)d_in[0];
    const float* pos = (const float*)d_in[1];
    const float* wq  = (const float*)d_in[2];
    const float* wk  = (const float*)d_in[3];
    const float* wv  = (const float*)d_in[4];
    const float* pw1 = (const float*)d_in[5];
    const float* pb1 = (const float*)d_in[6];
    const float* pw2 = (const float*)d_in[7];
    const float* pb2 = (const float*)d_in[8];
    const float* aw1 = (const float*)d_in[9];
    const float* ab1 = (const float*)d_in[10];
    const float* aw2 = (const float*)d_in[11];
    const float* ab2 = (const float*)d_in[12];
    const float* fw  = (const float*)d_in[13];
    const float* fb  = (const float*)d_in[14];
    (void)in_sizes; (void)n_in; (void)out_size;

    float *q, *k, *v, *agg, *buf1, *buf2, *pe, *wr, *xr;
    cudaGetSymbolAddress((void**)&q,    g_q);
    cudaGetSymbolAddress((void**)&k,    g_k);
    cudaGetSymbolAddress((void**)&v,    g_v);
    cudaGetSymbolAddress((void**)&agg,  g_agg);
    cudaGetSymbolAddress((void**)&buf1, g_buf1);
    cudaGetSymbolAddress((void**)&buf2, g_buf2);
    cudaGetSymbolAddress((void**)&pe,   g_pe);
    cudaGetSymbolAddress((void**)&wr,   g_wr);
    cudaGetSymbolAddress((void**)&xr,   g_xr);

    cudaFuncSetAttribute(gemm_tf32_kernel,
                         cudaFuncAttributeMaxDynamicSharedMemorySize, GEMM_SMEM_BYTES);
    cudaFuncSetAttribute(knn_kernel,
                         cudaFuncAttributeMaxDynamicSharedMemorySize, KNN_SMEM_BYTES);

    const float* wq_r  = wr;
    const float* wk_r  = wr + 1 * 65536;
    const float* wv_r  = wr + 2 * 65536;
    const float* pw2_r = wr + 3 * 65536;
    const float* aw1_r = wr + 4 * 65536;
    const float* aw2_r = wr + 5 * 65536;
    const float* fw_r  = wr + 6 * 65536;

    dim3 blk(256);
    dim3 gSmall(2, BNP / 128);     // (2, 64)
    dim3 gBig(2, M2 / 128);        // (2, 1024)

    // pre-round weights + x to tf32
    RoundSrcs rs;
    rs.p[0] = wq;  rs.p[1] = wk;  rs.p[2] = wv;  rs.p[3] = pw2;
    rs.p[4] = aw1; rs.p[5] = aw2; rs.p[6] = fw;  rs.p[7] = x;
    round_prep_kernel<<<(7 * 16384 + BNP * DIMV / 4 + 255) / 256, blk>>>(rs);

    // q, k, v projections
    gemm_tf32_kernel<<<gSmall, blk, GEMM_SMEM_BYTES>>>(xr, wq_r, nullptr, nullptr, q, BNP, 0, 0);
    gemm_tf32_kernel<<<gSmall, blk, GEMM_SMEM_BYTES>>>(xr, wk_r, nullptr, nullptr, k, BNP, 0, 0);
    gemm_tf32_kernel<<<gSmall, blk, GEMM_SMEM_BYTES>>>(xr, wv_r, nullptr, nullptr, v, BNP, 0, 0);

    // knn
    knn_kernel<<<BNP / 8, blk, KNN_SMEM_BYTES>>>(pos);

    // pos_enc path: h = relu(rel@pw1+pb1) ; pe = h@pw2+pb2
    build_h_kernel<<<M2, blk>>>(pos, pw1, pb1);
    gemm_tf32_kernel<<<gBig, blk, GEMM_SMEM_BYTES>>>(buf1, pw2_r, pb2, nullptr, pe, M2, 0, 0);

    // attention MLP: a_in = q - k[idx] + pe ; h2 = relu(a_in@aw1+ab1) ; a2 = h2@aw2+ab2
    a_in_kernel<<<M2, blk>>>();
    gemm_tf32_kernel<<<gBig, blk, GEMM_SMEM_BYTES>>>(buf1, aw1_r, ab1, nullptr, buf2, M2, 1, 1);
    gemm_tf32_kernel<<<gBig, blk, GEMM_SMEM_BYTES>>>(buf2, aw2_r, ab2, nullptr, buf1, M2, 0, 0);

    // softmax over K + aggregate
    softmax_agg_kernel<<<BNP, blk>>>();

    // out = agg@fw + fb + x
    gemm_tf32_kernel<<<gSmall, blk, GEMM_SMEM_BYTES>>>(agg, fw_r, fb, x, (float*)d_out, BNP, 0, 0);
}

// round 4
// speedup vs baseline: 3.8090x; 1.5730x over previous
#include <cuda_runtime.h>
#include <cuda_bf16.h>
#include <math.h>
#include <stdint.h>

// Problem constants
#define BB   2
#define NN   4096
#define BNP  (BB*NN)        // 8192 rows
#define DIMV 256
#define KNNV 16
#define M2   (BNP*KNNV)     // 131072 rows for per-neighbor tensors

typedef __nv_bfloat16 bf16;
typedef __nv_bfloat162 bf162;

// -------------------- scratch (no allocations allowed) --------------------
__device__ float g_qa [BNP*DIMV];          // x @ (wq@aw1)
__device__ float g_ka [BNP*DIMV];          // x @ (wk@aw1)
__device__ bf16  g_v  [BNP*DIMV];
__device__ bf16  g_agg[BNP*DIMV];
__device__ int   g_idx[M2];
__device__ bf16  g_h  [(size_t)M2*DIMV];   // relu(rel@pw1+pb1)
__device__ bf16  g_pe [(size_t)M2*DIMV];   // h@pw2+pb2
__device__ bf16  g_h2 [(size_t)M2*DIMV];   // relu(h@Wpa + qa - ka + bpa)
__device__ bf16  g_a2 [(size_t)M2*DIMV];   // h2@aw2+ab2
__device__ bf16  g_wt [7*DIMV*DIMV];       // transposed bf16 weights [n][k]
__device__ bf16  g_xb [BNP*DIMV];          // bf16 x
__device__ float g_bpa[DIMV];              // pb2@aw1 + ab1

// weight slots in g_wt
#define WT_WV  0
#define WT_PW2 1
#define WT_AW2 2
#define WT_FW  3
#define WT_WQA 4
#define WT_WKA 5
#define WT_WPA 6

// ==================== bf16 tensor-core GEMM ====================
// C = epilogue(A@B + ...).  A: M x 256 bf16 row-major.
// Bt: 256 x 256 bf16, stored TRANSPOSED as [n][k].
// CTA tile 128x128, BK=64, 8 warps (2x4), mma.m16n8k16.bf16.

#define BKV   64
#define ASTR  72                    // bf16 elems per smem row (144B, conflict-free)
#define TBUF  (128*ASTR)            // one tile buffer (bf16 elems)
#define GEMM_SMEM_BYTES (4*TBUF*2)  // A x2 + B x2 = 73728 B

// epilogue flags
#define F_RELU 1
#define F_OBF  2
#define F_QK   4

__device__ __forceinline__ void cp16b(bf16* s, const bf16* g) {
    uint32_t sa = (uint32_t)__cvta_generic_to_shared(s);
    asm volatile("cp.async.cg.shared.global [%0], [%1], 16;\n" :: "r"(sa), "l"(g));
}

__global__ __launch_bounds__(256)
void gemm_bf16_kernel(const bf16* __restrict__ A, const bf16* __restrict__ Bt,
                      const float* __restrict__ bias,
                      const float* __restrict__ qa, const float* __restrict__ ka,
                      const float* __restrict__ resid,
                      void* __restrict__ Cout, int M, int flags)
{
    extern __shared__ bf16 smem[];
    bf16* As = smem;              // [2][128][ASTR]
    bf16* Bs = smem + 2 * TBUF;   // [2][128][ASTR]

    const int tid  = threadIdx.x;
    const int lane = tid & 31;
    const int warp = tid >> 5;
    const int wm   = warp >> 2;       // 0..1  -> 64 rows
    const int wn   = warp & 3;        // 0..3  -> 32 cols
    const int bm   = blockIdx.y * 128;
    const int bn   = blockIdx.x * 128;

    const int g  = lane >> 2;         // groupID 0..7
    const int tg = lane & 3;          // thread-in-group 0..3

    float acc[4][4][4];
#pragma unroll
    for (int i = 0; i < 4; ++i)
#pragma unroll
        for (int j = 0; j < 4; ++j)
#pragma unroll
            for (int c = 0; c < 4; ++c) acc[i][j][c] = 0.f;

    auto load_tile = [&](int buf, int k0) {
#pragma unroll
        for (int u = 0; u < 4; ++u) {
            int idx = tid + u * 256;          // 0..1023
            int row = idx >> 3;               // 0..127
            int c8  = (idx & 7) * 8;          // 0..56 (bf16 elems)
            cp16b(&As[buf * TBUF + row * ASTR + c8],
                  A + (size_t)(bm + row) * 256 + k0 + c8);
        }
#pragma unroll
        for (int u = 0; u < 4; ++u) {
            int idx = tid + u * 256;
            int row = idx >> 3;               // n index 0..127
            int c8  = (idx & 7) * 8;
            cp16b(&Bs[buf * TBUF + row * ASTR + c8],
                  Bt + (size_t)(bn + row) * 256 + k0 + c8);
        }
        asm volatile("cp.async.commit_group;\n");
    };

    load_tile(0, 0);

    for (int t = 0; t < 4; ++t) {
        const int buf = t & 1;
        if (t < 3) {
            load_tile(buf ^ 1, (t + 1) * BKV);
            asm volatile("cp.async.wait_group 1;\n");
        } else {
            asm volatile("cp.async.wait_group 0;\n");
        }
        __syncthreads();

        const bf16* Ab = As + buf * TBUF;
        const bf16* Bb = Bs + buf * TBUF;

#pragma unroll
        for (int ks = 0; ks < 4; ++ks) {
            const int k0 = ks * 16;
            uint32_t af[4][4], bfr[4][2];
#pragma unroll
            for (int mt = 0; mt < 4; ++mt) {
                int row = wm * 64 + mt * 16 + g;
                const bf16* p0 = Ab + row * ASTR + k0 + 2 * tg;
                const bf16* p1 = Ab + (row + 8) * ASTR + k0 + 2 * tg;
                af[mt][0] = *(const uint32_t*)(p0);
                af[mt][1] = *(const uint32_t*)(p1);
                af[mt][2] = *(const uint32_t*)(p0 + 8);
                af[mt][3] = *(const uint32_t*)(p1 + 8);
            }
#pragma unroll
            for (int nt = 0; nt < 4; ++nt) {
                int col = wn * 32 + nt * 8 + g;
                const bf16* bp = Bb + col * ASTR + k0 + 2 * tg;
                bfr[nt][0] = *(const uint32_t*)(bp);
                bfr[nt][1] = *(const uint32_t*)(bp + 8);
            }
#pragma unroll
            for (int mt = 0; mt < 4; ++mt)
#pragma unroll
                for (int nt = 0; nt < 4; ++nt) {
                    asm volatile(
                        "mma.sync.aligned.m16n8k16.row.col.f32.bf16.bf16.f32 "
                        "{%0,%1,%2,%3}, {%4,%5,%6,%7}, {%8,%9}, {%0,%1,%2,%3};\n"
                        : "+f"(acc[mt][nt][0]), "+f"(acc[mt][nt][1]),
                          "+f"(acc[mt][nt][2]), "+f"(acc[mt][nt][3])
                        : "r"(af[mt][0]), "r"(af[mt][1]), "r"(af[mt][2]), "r"(af[mt][3]),
                          "r"(bfr[nt][0]), "r"(bfr[nt][1]));
                }
        }
        __syncthreads();
    }

    // epilogue
    const bool doRelu = flags & F_RELU;
    const bool obf    = flags & F_OBF;
    const bool doQK   = flags & F_QK;
#pragma unroll
    for (int mt = 0; mt < 4; ++mt) {
#pragma unroll
        for (int nt = 0; nt < 4; ++nt) {
            int row0 = bm + wm * 64 + mt * 16 + g;
            int col0 = bn + wn * 32 + nt * 8 + 2 * tg;
#pragma unroll
            for (int h = 0; h < 2; ++h) {
                int row = row0 + h * 8;
                float c0 = acc[mt][nt][2 * h];
                float c1 = acc[mt][nt][2 * h + 1];
                if (bias) { c0 += bias[col0]; c1 += bias[col0 + 1]; }
                if (doQK) {
                    int n = row >> 4;
                    int r = g_idx[row];
                    float2 qv = *(const float2*)(qa + (size_t)n * 256 + col0);
                    float2 kv = *(const float2*)(ka + (size_t)r * 256 + col0);
                    c0 += qv.x - kv.x;
                    c1 += qv.y - kv.y;
                }
                if (doRelu) { c0 = fmaxf(c0, 0.f); c1 = fmaxf(c1, 0.f); }
                if (obf) {
                    *(bf162*)((bf16*)Cout + (size_t)row * 256 + col0) =
                        __floats2bfloat162_rn(c0, c1);
                } else {
                    if (resid) {
                        c0 += resid[(size_t)row * 256 + col0];
                        c1 += resid[(size_t)row * 256 + col0 + 1];
                    }
                    *(float2*)((float*)Cout + (size_t)row * 256 + col0) =
                        make_float2(c0, c1);
                }
            }
        }
    }
}

// -------------------- prep: convert / transpose / fold --------------------
struct WSrcs { const float* p[4]; };   // wv, pw2, aw2, fw

__global__ __launch_bounds__(256)
void conv_weights_kernel(WSrcs ws)
{
    const int sel = blockIdx.x >> 8;      // 0..3
    const int n   = blockIdx.x & 255;
    const int k   = threadIdx.x;
    g_wt[(size_t)sel * 65536 + n * 256 + k] =
        __float2bfloat16_rn(ws.p[sel][k * 256 + n]);
}

// Wqa = wq@aw1, Wka = wk@aw1, Wpa = pw2@aw1 (stored transposed, bf16),
// bpa = pb2@aw1 + ab1 (fp32)
__global__ __launch_bounds__(256)
void fold_kernel(const float* __restrict__ wq, const float* __restrict__ wk,
                 const float* __restrict__ pw2, const float* __restrict__ aw1,
                 const float* __restrict__ pb2, const float* __restrict__ ab1)
{
    const int b = blockIdx.x;
    const int j = threadIdx.x;
    if (b < 768) {
        const int sel = b >> 8;
        const int i   = b & 255;
        const float* src = (sel == 0) ? wq : (sel == 1) ? wk : pw2;
        float s = 0.f;
        for (int d = 0; d < 256; ++d)
            s = fmaf(src[i * 256 + d], aw1[d * 256 + j], s);
        g_wt[(size_t)(WT_WQA + sel) * 65536 + j * 256 + i] = __float2bfloat16_rn(s);
    } else {
        float s = ab1[j];
        for (int d = 0; d < 256; ++d)
            s = fmaf(pb2[d], aw1[d * 256 + j], s);
        g_bpa[j] = s;
    }
}

__global__ __launch_bounds__(256)
void conv_x_kernel(const float* __restrict__ x)
{
    const int i4 = blockIdx.x * 256 + threadIdx.x;   // float4 index
    if (i4 < BNP * DIMV / 4) {
        float4 v = *(const float4*)(x + (size_t)i4 * 4);
        bf162* o = (bf162*)(g_xb + (size_t)i4 * 4);
        o[0] = __floats2bfloat162_rn(v.x, v.y);
        o[1] = __floats2bfloat162_rn(v.z, v.w);
    }
}

// -------------------- KNN: warp-collective threshold top-16 --------------------
__device__ __forceinline__ bool dless(float d1, int i1, float d2, int i2) {
    return (d1 < d2) || (d1 == d2 && i1 < i2);
}

#define KNN_SMEM_BYTES (4 * NN * 4)

__global__ __launch_bounds__(256)
void knn_kernel(const float* __restrict__ pos)
{
    extern __shared__ float sm[];
    float* px = sm;
    float* py = sm + NN;
    float* pz = sm + 2 * NN;
    float* sj = sm + 3 * NN;

    const int b = blockIdx.x >> 9;             // 512 blocks per batch
    const float* pb = pos + (size_t)b * NN * 3;
    for (int j = threadIdx.x; j < NN; j += 256) {
        float x = pb[3 * j], y = pb[3 * j + 1], z = pb[3 * j + 2];
        px[j] = x; py[j] = y; pz[j] = z;
        sj[j] = x * x + y * y + z * z;
    }
    __syncthreads();

    const int warp = threadIdx.x >> 5, lane = threadIdx.x & 31;
    const int q  = blockIdx.x * 8 + warp;       // global query
    const int ql = q & (NN - 1);
    const float qx = px[ql], qy = py[ql], qz = pz[ql];
    const float qsq = sj[ql];

    const unsigned FULL = 0xffffffffu;
    float ld  = 3.4e38f; int li   = 0x7fffffff;
    float tau = 3.4e38f; int taui = 0x7fffffff;

#define KNN_INSERT(cd, cj)                                             \
    {                                                                  \
        bool keep = dless(ld, li, (cd), (cj));                         \
        unsigned bal = __ballot_sync(FULL, keep) & 0xffffu;            \
        int p = __popc(bal);                                           \
        float pd = __shfl_up_sync(FULL, ld, 1);                        \
        int   pi = __shfl_up_sync(FULL, li, 1);                        \
        if (lane == p) { ld = (cd); li = (cj); }                       \
        else if (lane > p && lane < 16) { ld = pd; li = pi; }          \
        tau  = __shfl_sync(FULL, ld, 15);                              \
        taui = __shfl_sync(FULL, li, 15);                              \
    }

#define KNN_HANDLE(dd, jj)                                             \
    {                                                                  \
        unsigned any = __ballot_sync(FULL, dless(dd, jj, tau, taui));  \
        while (any) {                                                  \
            int src = __ffs(any) - 1; any &= any - 1;                  \
            float cd = __shfl_sync(FULL, dd, src);                     \
            int   cj = __shfl_sync(FULL, jj, src);                     \
            if (dless(cd, cj, tau, taui)) KNN_INSERT(cd, cj);          \
        }                                                              \
    }

    for (int base = 0; base < NN; base += 128) {
        const int j0 = base + lane;
        const int j1 = j0 + 32;
        const int j2 = j0 + 64;
        const int j3 = j0 + 96;
        float d0 = qsq + sj[j0] - 2.f * (qx * px[j0] + qy * py[j0] + qz * pz[j0]);
        float d1 = qsq + sj[j1] - 2.f * (qx * px[j1] + qy * py[j1] + qz * pz[j1]);
        float d2 = qsq + sj[j2] - 2.f * (qx * px[j2] + qy * py[j2] + qz * pz[j2]);
        float d3 = qsq + sj[j3] - 2.f * (qx * px[j3] + qy * py[j3] + qz * pz[j3]);
        KNN_HANDLE(d0, j0)
        KNN_HANDLE(d1, j1)
        KNN_HANDLE(d2, j2)
        KNN_HANDLE(d3, j3)
    }

    if (lane < KNNV) g_idx[q * KNNV + lane] = b * NN + li;
#undef KNN_INSERT
#undef KNN_HANDLE
}

// ---------- h = relu(rel @ pw1 + pb1), rel = pos[n] - pos[neigh] ----------
__global__ __launch_bounds__(256)
void build_h_kernel(const float* __restrict__ pos, const float* __restrict__ pw1,
                    const float* __restrict__ pb1)
{
    const int m = blockIdx.x;          // 0..M2-1
    const int d = threadIdx.x;
    const int n = m >> 4;              // global query row
    const int r = g_idx[m];            // global neighbor row
    const float rx = pos[3 * n]     - pos[3 * r];
    const float ry = pos[3 * n + 1] - pos[3 * r + 1];
    const float rz = pos[3 * n + 2] - pos[3 * r + 2];
    float v = pb1[d] + rx * pw1[d] + ry * pw1[DIMV + d] + rz * pw1[2 * DIMV + d];
    g_h[(size_t)m * DIMV + d] = __float2bfloat16_rn(fmaxf(v, 0.f));
}

// ---------- softmax over K (per channel) + weighted aggregate ----------
__global__ __launch_bounds__(256)
void softmax_agg_kernel()
{
    const int n = blockIdx.x;          // 0..8191
    const int d = threadIdx.x;
    const float inv_scale = 1.0f / 16.0f;   // 1/sqrt(256)

    float a[KNNV];
    float mx = -3.4e38f;
#pragma unroll
    for (int kk = 0; kk < KNNV; ++kk) {
        a[kk] = __bfloat162float(g_a2[((size_t)(n * KNNV + kk)) * DIMV + d]) * inv_scale;
        mx = fmaxf(mx, a[kk]);
    }
    float s = 0.f;
#pragma unroll
    for (int kk = 0; kk < KNNV; ++kk) {
        float e = expf(a[kk] - mx);
        a[kk] = e;
        s += e;
    }
    const float invs = 1.f / s;
    float acc = 0.f;
#pragma unroll
    for (int kk = 0; kk < KNNV; ++kk) {
        int r = g_idx[n * KNNV + kk];
        acc += a[kk] * (__bfloat162float(g_v[(size_t)r * DIMV + d]) +
                        __bfloat162float(g_pe[((size_t)(n * KNNV + kk)) * DIMV + d]));
    }
    g_agg[(size_t)n * DIMV + d] = __float2bfloat16_rn(acc * invs);
}

// -------------------- launch --------------------
extern "C" void kernel_launch(void* const* d_in, const int* in_sizes, int n_in,
                              void* d_out, int out_size)
{
    const float* x   = (const float*)d_in[0];
    const float* pos = (const float*)d_in[1];
    const float* wq  = (const float*)d_in[2];
    const float* wk  = (const float*)d_in[3];
    const float* wv  = (const float*)d_in[4];
    const float* pw1 = (const float*)d_in[5];
    const float* pb1 = (const float*)d_in[6];
    const float* pw2 = (const float*)d_in[7];
    const float* pb2 = (const float*)d_in[8];
    const float* aw1 = (const float*)d_in[9];
    const float* ab1 = (const float*)d_in[10];
    const float* aw2 = (const float*)d_in[11];
    const float* ab2 = (const float*)d_in[12];
    const float* fw  = (const float*)d_in[13];
    const float* fb  = (const float*)d_in[14];
    (void)in_sizes; (void)n_in; (void)out_size;

    float *qa, *ka, *bpa;
    bf16 *v, *agg, *h, *pe, *h2, *a2, *wt, *xb;
    cudaGetSymbolAddress((void**)&qa,  g_qa);
    cudaGetSymbolAddress((void**)&ka,  g_ka);
    cudaGetSymbolAddress((void**)&v,   g_v);
    cudaGetSymbolAddress((void**)&agg, g_agg);
    cudaGetSymbolAddress((void**)&h,   g_h);
    cudaGetSymbolAddress((void**)&pe,  g_pe);
    cudaGetSymbolAddress((void**)&h2,  g_h2);
    cudaGetSymbolAddress((void**)&a2,  g_a2);
    cudaGetSymbolAddress((void**)&wt,  g_wt);
    cudaGetSymbolAddress((void**)&xb,  g_xb);
    cudaGetSymbolAddress((void**)&bpa, g_bpa);

    cudaFuncSetAttribute(gemm_bf16_kernel,
                         cudaFuncAttributeMaxDynamicSharedMemorySize, GEMM_SMEM_BYTES);
    cudaFuncSetAttribute(knn_kernel,
                         cudaFuncAttributeMaxDynamicSharedMemorySize, KNN_SMEM_BYTES);

    const bf16* wvt  = wt + (size_t)WT_WV  * 65536;
    const bf16* pw2t = wt + (size_t)WT_PW2 * 65536;
    const bf16* aw2t = wt + (size_t)WT_AW2 * 65536;
    const bf16* fwt  = wt + (size_t)WT_FW  * 65536;
    const bf16* wqat = wt + (size_t)WT_WQA * 65536;
    const bf16* wkat = wt + (size_t)WT_WKA * 65536;
    const bf16* wpat = wt + (size_t)WT_WPA * 65536;

    dim3 blk(256);
    dim3 gSmall(2, BNP / 128);     // (2, 64)
    dim3 gBig(2, M2 / 128);        // (2, 1024)

    // prep
    WSrcs ws; ws.p[0] = wv; ws.p[1] = pw2; ws.p[2] = aw2; ws.p[3] = fw;
    conv_weights_kernel<<<1024, blk>>>(ws);
    fold_kernel<<<769, blk>>>(wq, wk, pw2, aw1, pb2, ab1);
    conv_x_kernel<<<BNP * DIMV / 4 / 256, blk>>>(x);

    // qa, ka, v projections (8192 rows)
    gemm_bf16_kernel<<<gSmall, blk, GEMM_SMEM_BYTES>>>(xb, wqat, nullptr, nullptr, nullptr, nullptr, qa, BNP, 0);
    gemm_bf16_kernel<<<gSmall, blk, GEMM_SMEM_BYTES>>>(xb, wkat, nullptr, nullptr, nullptr, nullptr, ka, BNP, 0);
    gemm_bf16_kernel<<<gSmall, blk, GEMM_SMEM_BYTES>>>(xb, wvt,  nullptr, nullptr, nullptr, nullptr, v,  BNP, F_OBF);

    // knn
    knn_kernel<<<BNP / 8, blk, KNN_SMEM_BYTES>>>(pos);

    // h = relu(rel@pw1+pb1)
    build_h_kernel<<<M2, blk>>>(pos, pw1, pb1);

    // pe = h@pw2 + pb2
    gemm_bf16_kernel<<<gBig, blk, GEMM_SMEM_BYTES>>>(h, pw2t, pb2, nullptr, nullptr, nullptr, pe, M2, F_OBF);

    // h2 = relu(h@Wpa + bpa + qa[n] - ka[r])
    gemm_bf16_kernel<<<gBig, blk, GEMM_SMEM_BYTES>>>(h, wpat, bpa, qa, ka, nullptr, h2, M2, F_OBF | F_RELU | F_QK);

    // a2 = h2@aw2 + ab2
    gemm_bf16_kernel<<<gBig, blk, GEMM_SMEM_BYTES>>>(h2, aw2t, ab2, nullptr, nullptr, nullptr, a2, M2, F_OBF);

    // softmax over K + aggregate
    softmax_agg_kernel<<<BNP, blk>>>();

    // out = agg@fw + fb + x
    gemm_bf16_kernel<<<gSmall, blk, GEMM_SMEM_BYTES>>>(agg, fwt, fb, nullptr, nullptr, x, (float*)d_out, BNP, 0);
}